// round 7
// baseline (speedup 1.0000x reference)
#include <cuda_runtime.h>
#include <cuda_bf16.h>
#include <cstdint>

#define PITCH 1026
// g_pos[n][i][t + s(i)], s(i)=(i+1)&1 -> flash shifted reads are 8B aligned
__device__ float g_pos[(size_t)64 * 1024 * PITCH];

// ------------------------------ helpers -----------------------------------
__device__ __forceinline__ uint32_t smem_u32(const void* p) {
    uint32_t a;
    asm("{ .reg .u64 t; cvta.to.shared.u64 t, %1; cvt.u32.u64 %0, t; }" : "=r"(a) : "l"(p));
    return a;
}
__device__ __forceinline__ void ldsm4(uint32_t* r, uint32_t a) {
    asm volatile("ldmatrix.sync.aligned.m8n8.x4.shared.b16 {%0,%1,%2,%3}, [%4];"
        : "=r"(r[0]), "=r"(r[1]), "=r"(r[2]), "=r"(r[3]) : "r"(a));
}
__device__ __forceinline__ void ldsm2(uint32_t* r, uint32_t a) {
    asm volatile("ldmatrix.sync.aligned.m8n8.x2.shared.b16 {%0,%1}, [%2];"
        : "=r"(r[0]), "=r"(r[1]) : "r"(a));
}
__device__ __forceinline__ void mma16816(float* c, const uint32_t* a, const uint32_t* b) {
    asm volatile("mma.sync.aligned.m16n8k16.row.col.f32.bf16.bf16.f32 "
        "{%0,%1,%2,%3}, {%4,%5,%6,%7}, {%8,%9}, {%0,%1,%2,%3};"
        : "+f"(c[0]), "+f"(c[1]), "+f"(c[2]), "+f"(c[3])
        : "r"(a[0]), "r"(a[1]), "r"(a[2]), "r"(a[3]), "r"(b[0]), "r"(b[1]));
}
__device__ __forceinline__ void splitpair(float a, float b, uint32_t& hi, uint32_t& lo) {
    __nv_bfloat16 ah = __float2bfloat16_rn(a), bh = __float2bfloat16_rn(b);
    __nv_bfloat16 al = __float2bfloat16_rn(a - __bfloat162float(ah));
    __nv_bfloat16 bl = __float2bfloat16_rn(b - __bfloat162float(bh));
    __nv_bfloat162 h2, l2; h2.x = ah; h2.y = bh; l2.x = al; l2.y = bl;
    hi = *reinterpret_cast<uint32_t*>(&h2); lo = *reinterpret_cast<uint32_t*>(&l2);
}
__device__ __forceinline__ float posval(const float* pb, int i, int j) {
    if (j <= i)     return pb[(size_t)i * PITCH + (1023 + j - i + ((i + 1) & 1))];
    if (j == i + 1) return 0.0f;
    return pb[(size_t)(i + 1) * PITCH + (j - i - 2 + ((i + 2) & 1))];
}
__device__ __forceinline__ float2 pos2(const float* pb, int i, int j) {
    if (j + 1 <= i)
        return *(const float2*)(pb + (size_t)i * PITCH + (1023 - i + ((i + 1) & 1)) + j);
    if (j >= i + 2)
        return *(const float2*)(pb + (size_t)(i + 1) * PITCH + (((i + 2) & 1) - i - 2) + j);
    float2 r;
    r.x = posval(pb, i, j);
    r.y = posval(pb, i, j + 1);
    return r;
}

// ---------------------------------------------------------------------------
// Kernel 1: g_pos(shifted) = (q*0.125 + vbias) . R^T  via mma.sync bf16x3.
// Tile 128(i) x 64(t). grid (16 t, 8 i, 64 n), 256 thr = 8 warps 2(M)x4(N).
// ---------------------------------------------------------------------------
#define PQH 0
#define PQL 18432
#define PRH 36864
#define PRL 46080
#define POS_SMEM 55296

__global__ __launch_bounds__(256)
void pos_mma(const float* __restrict__ q, const float* __restrict__ vbias,
             const float* __restrict__ R)
{
    extern __shared__ char cb[];
    uint32_t sb = smem_u32(cb);

    const int tid = threadIdx.x, lane = tid & 31, wid = tid >> 5;
    const int wm = wid >> 2, wn = wid & 3;
    const int n = blockIdx.z, h = n & 15;
    const int i0 = blockIdx.y << 7, t0 = blockIdx.x << 6;

    const float* qb = q + (size_t)n * 65536 + (size_t)i0 * 64;
    const float* rb = R + (size_t)h * (2048 * 64) + (size_t)t0 * 64;

    #pragma unroll
    for (int it = 0; it < 8; ++it) {
        int fi = it * 256 + tid;
        int r = fi >> 4, d = (fi & 15) << 2;
        float4 f = *(const float4*)(qb + r * 64 + d);
        float4 bs = *(const float4*)(vbias + h * 64 + d);
        f.x = f.x * 0.125f + bs.x; f.y = f.y * 0.125f + bs.y;
        f.z = f.z * 0.125f + bs.z; f.w = f.w * 0.125f + bs.w;
        uint2 H, L;
        splitpair(f.x, f.y, H.x, L.x); splitpair(f.z, f.w, H.y, L.y);
        *(uint2*)(cb + PQH + r * 144 + d * 2) = H;
        *(uint2*)(cb + PQL + r * 144 + d * 2) = L;
    }
    #pragma unroll
    for (int it = 0; it < 4; ++it) {
        int fi = it * 256 + tid;
        int r = fi >> 4, d = (fi & 15) << 2;
        float4 g = *(const float4*)(rb + r * 64 + d);
        uint2 H, L;
        splitpair(g.x, g.y, H.x, L.x); splitpair(g.z, g.w, H.y, L.y);
        *(uint2*)(cb + PRH + r * 144 + d * 2) = H;
        *(uint2*)(cb + PRL + r * 144 + d * 2) = L;
    }
    __syncthreads();

    float C[4][2][4] = {};

    #pragma unroll
    for (int ks = 0; ks < 4; ++ks) {
        uint32_t a[4][4], bh[2][2], bl[2][2];
        #pragma unroll
        for (int mt = 0; mt < 4; ++mt)
            ldsm4(a[mt], sb + PQH + (wm * 64 + mt * 16 + (lane & 15)) * 144 +
                         (ks * 16 + ((lane >> 4) << 3)) * 2);
        #pragma unroll
        for (int nt = 0; nt < 2; ++nt) {
            uint32_t ao = (wn * 16 + nt * 8 + (lane & 7)) * 144 +
                          (ks * 16 + (((lane >> 3) & 1) << 3)) * 2;
            ldsm2(bh[nt], sb + PRH + ao);
            ldsm2(bl[nt], sb + PRL + ao);
        }
        #pragma unroll
        for (int mt = 0; mt < 4; ++mt)
            #pragma unroll
            for (int nt = 0; nt < 2; ++nt) {
                mma16816(C[mt][nt], a[mt], bh[nt]);
                mma16816(C[mt][nt], a[mt], bl[nt]);
            }
    }
    #pragma unroll
    for (int ks = 0; ks < 4; ++ks) {
        uint32_t a[4][4], bh[2][2];
        #pragma unroll
        for (int mt = 0; mt < 4; ++mt)
            ldsm4(a[mt], sb + PQL + (wm * 64 + mt * 16 + (lane & 15)) * 144 +
                         (ks * 16 + ((lane >> 4) << 3)) * 2);
        #pragma unroll
        for (int nt = 0; nt < 2; ++nt)
            ldsm2(bh[nt], sb + PRH + (wn * 16 + nt * 8 + (lane & 7)) * 144 +
                          (ks * 16 + (((lane >> 3) & 1) << 3)) * 2);
        #pragma unroll
        for (int mt = 0; mt < 4; ++mt)
            #pragma unroll
            for (int nt = 0; nt < 2; ++nt)
                mma16816(C[mt][nt], a[mt], bh[nt]);
    }

    float* gpn = g_pos + (size_t)n * (1024 * PITCH);
    #pragma unroll
    for (int mt = 0; mt < 4; ++mt) {
        const int i1 = i0 + wm * 64 + mt * 16 + (lane >> 2);
        const int i2 = i1 + 8;
        float* r1 = gpn + (size_t)i1 * PITCH + ((i1 + 1) & 1);
        float* r2 = gpn + (size_t)i2 * PITCH + ((i2 + 1) & 1);
        #pragma unroll
        for (int nt = 0; nt < 2; ++nt) {
            const int jc = t0 + wn * 16 + nt * 8 + ((lane & 3) << 1);
            r1[jc] = C[mt][nt][0]; r1[jc + 1] = C[mt][nt][1];
            r2[jc] = C[mt][nt][2]; r2[jc + 1] = C[mt][nt][3];
        }
    }
}

// ---------------------------------------------------------------------------
// Kernel 2: flash attention via mma.sync bf16x3. BM=128(i), BN=64(j), 16 iters.
// 512 threads = 16 warps 4(M)x4(N); warp tile 32(i)x16(j) / 32(i)x16(d).
// grid (8 i-tiles, 64 n). smem 112640.
// ---------------------------------------------------------------------------
#define QUH_O 0
#define QUL_O 18432
#define KH_O  36864
#define KL_O  46080
#define VTH_O 55296
#define VTL_O 64512
#define PH_O  73728
#define PL_O  92160
#define LS_O  110592
#define FLASH_SMEM (LS_O + 2048)

__global__ __launch_bounds__(512)
void flash_mma(const float* __restrict__ q, const float* __restrict__ k,
               const float* __restrict__ v, const float* __restrict__ ubias,
               float* __restrict__ out)
{
    extern __shared__ char cb[];
    uint32_t sb = smem_u32(cb);

    const int tid = threadIdx.x, lane = tid & 31, wid = tid >> 5;
    const int wm = wid >> 2, wn = wid & 3;
    const int n = blockIdx.y, h = n & 15;
    const int i0 = blockIdx.x << 7;

    // stage Qu = q*0.125 + u_bias (hi/lo)
    const float* qb = q + (size_t)n * 65536 + (size_t)i0 * 64;
    #pragma unroll
    for (int it = 0; it < 4; ++it) {
        int fi = it * 512 + tid;
        int r = fi >> 4, d = (fi & 15) << 2;
        float4 f = *(const float4*)(qb + r * 64 + d);
        float4 bs = *(const float4*)(ubias + h * 64 + d);
        f.x = f.x * 0.125f + bs.x; f.y = f.y * 0.125f + bs.y;
        f.z = f.z * 0.125f + bs.z; f.w = f.w * 0.125f + bs.w;
        uint2 H, L;
        splitpair(f.x, f.y, H.x, L.x); splitpair(f.z, f.w, H.y, L.y);
        *(uint2*)(cb + QUH_O + r * 144 + d * 2) = H;
        *(uint2*)(cb + QUL_O + r * 144 + d * 2) = L;
    }

    float oC[2][2][4] = {};
    float ls[4] = {};
    const float* pb  = g_pos + (size_t)n * (1024 * PITCH);
    const float* kb0 = k + (size_t)n * 65536;
    const float* vb0 = v + (size_t)n * 65536;

    for (int kt = 0; kt < 16; ++kt) {
        __syncthreads();   // prev PV done reading P/Vt/K before restage

        // ---- prefetch shifted pos values (latency overlaps staging) ----
        float pr[2][2][4];
        #pragma unroll
        for (int mt = 0; mt < 2; ++mt) {
            const int ir1 = wm * 32 + mt * 16 + (lane >> 2);
            const int i1 = i0 + ir1, i2 = i1 + 8;
            #pragma unroll
            for (int nt = 0; nt < 2; ++nt) {
                const int j = (kt << 6) + wn * 16 + nt * 8 + ((lane & 3) << 1);
                float2 pp = pos2(pb, i1, j);
                pr[mt][nt][0] = pp.x; pr[mt][nt][1] = pp.y;
                pp = pos2(pb, i2, j);
                pr[mt][nt][2] = pp.x; pr[mt][nt][3] = pp.y;
            }
        }

        // ---- stage K (hi/lo, [j][72]bf16) and V^T (hi/lo, [d][72]bf16) ----
        const float* kb = kb0 + ((size_t)kt << 12);
        const float* vb = vb0 + ((size_t)kt << 12);
        #pragma unroll
        for (int it = 0; it < 2; ++it) {
            int fi = it * 512 + tid;
            int r = fi >> 4, d = (fi & 15) << 2;
            float4 f = *(const float4*)(kb + r * 64 + d);
            uint2 H, L;
            splitpair(f.x, f.y, H.x, L.x); splitpair(f.z, f.w, H.y, L.y);
            *(uint2*)(cb + KH_O + r * 144 + d * 2) = H;
            *(uint2*)(cb + KL_O + r * 144 + d * 2) = L;
            float4 g = *(const float4*)(vb + r * 64 + d);
            float gv[4] = {g.x, g.y, g.z, g.w};
            #pragma unroll
            for (int rr = 0; rr < 4; ++rr) {
                int dd = d + rr;
                __nv_bfloat16 hh = __float2bfloat16_rn(gv[rr]);
                __nv_bfloat16 ll = __float2bfloat16_rn(gv[rr] - __bfloat162float(hh));
                *(__nv_bfloat16*)(cb + VTH_O + dd * 144 + r * 2) = hh;
                *(__nv_bfloat16*)(cb + VTL_O + dd * 144 + r * 2) = ll;
            }
        }
        __syncthreads();

        // ---- S = Qu . K^T  (bf16x3) ----
        float sC[2][2][4] = {};
        #pragma unroll
        for (int ks = 0; ks < 4; ++ks) {
            uint32_t a[2][4], bh[2][2], bl[2][2];
            #pragma unroll
            for (int mt = 0; mt < 2; ++mt)
                ldsm4(a[mt], sb + QUH_O + (wm * 32 + mt * 16 + (lane & 15)) * 144 +
                             (ks * 16 + ((lane >> 4) << 3)) * 2);
            #pragma unroll
            for (int nt = 0; nt < 2; ++nt) {
                uint32_t ao = (wn * 16 + nt * 8 + (lane & 7)) * 144 +
                              (ks * 16 + (((lane >> 3) & 1) << 3)) * 2;
                ldsm2(bh[nt], sb + KH_O + ao);
                ldsm2(bl[nt], sb + KL_O + ao);
            }
            #pragma unroll
            for (int mt = 0; mt < 2; ++mt)
                #pragma unroll
                for (int nt = 0; nt < 2; ++nt) {
                    mma16816(sC[mt][nt], a[mt], bh[nt]);
                    mma16816(sC[mt][nt], a[mt], bl[nt]);
                }
        }
        #pragma unroll
        for (int ks = 0; ks < 4; ++ks) {
            uint32_t a[2][4], bh[2][2];
            #pragma unroll
            for (int mt = 0; mt < 2; ++mt)
                ldsm4(a[mt], sb + QUL_O + (wm * 32 + mt * 16 + (lane & 15)) * 144 +
                             (ks * 16 + ((lane >> 4) << 3)) * 2);
            #pragma unroll
            for (int nt = 0; nt < 2; ++nt)
                ldsm2(bh[nt], sb + KH_O + (wn * 16 + nt * 8 + (lane & 7)) * 144 +
                              (ks * 16 + (((lane >> 3) & 1) << 3)) * 2);
            #pragma unroll
            for (int mt = 0; mt < 2; ++mt)
                #pragma unroll
                for (int nt = 0; nt < 2; ++nt)
                    mma16816(sC[mt][nt], a[mt], bh[nt]);
        }

        // ---- add prefetched pos, exp (no max-sub), split -> P smem ----
        #pragma unroll
        for (int mt = 0; mt < 2; ++mt) {
            const int ir1 = wm * 32 + mt * 16 + (lane >> 2);
            #pragma unroll
            for (int nt = 0; nt < 2; ++nt) {
                const int jloc = wn * 16 + nt * 8 + ((lane & 3) << 1);
                float e0 = __expf(sC[mt][nt][0] + pr[mt][nt][0]);
                float e1 = __expf(sC[mt][nt][1] + pr[mt][nt][1]);
                ls[mt * 2] += e0 + e1;
                uint32_t H, L;
                splitpair(e0, e1, H, L);
                *(uint32_t*)(cb + PH_O + ir1 * 144 + jloc * 2) = H;
                *(uint32_t*)(cb + PL_O + ir1 * 144 + jloc * 2) = L;
                e0 = __expf(sC[mt][nt][2] + pr[mt][nt][2]);
                e1 = __expf(sC[mt][nt][3] + pr[mt][nt][3]);
                ls[mt * 2 + 1] += e0 + e1;
                splitpair(e0, e1, H, L);
                *(uint32_t*)(cb + PH_O + (ir1 + 8) * 144 + jloc * 2) = H;
                *(uint32_t*)(cb + PL_O + (ir1 + 8) * 144 + jloc * 2) = L;
            }
        }
        __syncthreads();

        // ---- O += P . V  (bf16x3, fp32 reg accum), K-dim = 64 ----
        #pragma unroll
        for (int ks = 0; ks < 4; ++ks) {
            uint32_t aH[2][4], bH[2][2], bL[2][2];
            #pragma unroll
            for (int mt = 0; mt < 2; ++mt)
                ldsm4(aH[mt], sb + PH_O + (wm * 32 + mt * 16 + (lane & 15)) * 144 +
                              (ks * 16 + ((lane >> 4) << 3)) * 2);
            #pragma unroll
            for (int nt = 0; nt < 2; ++nt) {
                uint32_t ao = (wn * 16 + nt * 8 + (lane & 7)) * 144 +
                              (ks * 16 + (((lane >> 3) & 1) << 3)) * 2;
                ldsm2(bH[nt], sb + VTH_O + ao);
                ldsm2(bL[nt], sb + VTL_O + ao);
            }
            #pragma unroll
            for (int mt = 0; mt < 2; ++mt)
                #pragma unroll
                for (int nt = 0; nt < 2; ++nt) {
                    mma16816(oC[mt][nt], aH[mt], bH[nt]);
                    mma16816(oC[mt][nt], aH[mt], bL[nt]);
                }
        }
        #pragma unroll
        for (int ks = 0; ks < 4; ++ks) {
            uint32_t aL[2][4], bH[2][2];
            #pragma unroll
            for (int mt = 0; mt < 2; ++mt)
                ldsm4(aL[mt], sb + PL_O + (wm * 32 + mt * 16 + (lane & 15)) * 144 +
                              (ks * 16 + ((lane >> 4) << 3)) * 2);
            #pragma unroll
            for (int nt = 0; nt < 2; ++nt)
                ldsm2(bH[nt], sb + VTH_O + (wn * 16 + nt * 8 + (lane & 7)) * 144 +
                              (ks * 16 + (((lane >> 3) & 1) << 3)) * 2);
            #pragma unroll
            for (int mt = 0; mt < 2; ++mt)
                #pragma unroll
                for (int nt = 0; nt < 2; ++nt)
                    mma16816(oC[mt][nt], aL[mt], bH[nt]);
        }
    }

    // ---- row-sum reduction: quad lanes then 4 N-warps via smem ----
    float* lsm = (float*)(cb + LS_O);
    #pragma unroll
    for (int p = 0; p < 4; ++p) {
        float vv = ls[p];
        vv += __shfl_xor_sync(0xffffffffu, vv, 1);
        vv += __shfl_xor_sync(0xffffffffu, vv, 2);
        ls[p] = vv;
    }
    if ((lane & 3) == 0) {
        #pragma unroll
        for (int mt = 0; mt < 2; ++mt) {
            int ir1 = wm * 32 + mt * 16 + (lane >> 2);
            lsm[wn * 128 + ir1] = ls[mt * 2];
            lsm[wn * 128 + ir1 + 8] = ls[mt * 2 + 1];
        }
    }
    __syncthreads();

    // ---- normalize + store O ----
    #pragma unroll
    for (int mt = 0; mt < 2; ++mt) {
        const int ir1 = wm * 32 + mt * 16 + (lane >> 2);
        const int ir2 = ir1 + 8;
        float inv1 = 1.0f / (lsm[ir1] + lsm[128 + ir1] + lsm[256 + ir1] + lsm[384 + ir1]);
        float inv2 = 1.0f / (lsm[ir2] + lsm[128 + ir2] + lsm[256 + ir2] + lsm[384 + ir2]);
        #pragma unroll
        for (int nt = 0; nt < 2; ++nt) {
            const int dcol = wn * 16 + nt * 8 + ((lane & 3) << 1);
            float* o1 = out + (size_t)n * 65536 + (size_t)(i0 + ir1) * 64 + dcol;
            float* o2 = out + (size_t)n * 65536 + (size_t)(i0 + ir2) * 64 + dcol;
            o1[0] = oC[mt][nt][0] * inv1; o1[1] = oC[mt][nt][1] * inv1;
            o2[0] = oC[mt][nt][2] * inv2; o2[1] = oC[mt][nt][3] * inv2;
        }
    }
}

// ---------------------------------------------------------------------------
extern "C" void kernel_launch(void* const* d_in, const int* in_sizes, int n_in,
                              void* d_out, int out_size)
{
    const float* q  = (const float*)d_in[0];
    const float* k  = (const float*)d_in[1];
    const float* v  = (const float*)d_in[2];
    const float* ub = (const float*)d_in[3];
    const float* vb = (const float*)d_in[4];
    const float* R  = (const float*)d_in[5];
    float* out = (float*)d_out;

    cudaFuncSetAttribute(pos_mma, cudaFuncAttributeMaxDynamicSharedMemorySize, POS_SMEM);
    cudaFuncSetAttribute(flash_mma, cudaFuncAttributeMaxDynamicSharedMemorySize, FLASH_SMEM);

    pos_mma<<<dim3(16, 8, 64), 256, POS_SMEM>>>(q, vb, R);
    flash_mma<<<dim3(8, 64), 512, FLASH_SMEM>>>(q, k, v, ub, out);
}

// round 8
// speedup vs baseline: 1.0608x; 1.0608x over previous
#include <cuda_runtime.h>
#include <cuda_bf16.h>
#include <cstdint>

#define PITCH 1026
// g_pos[n][i][t + s(i)], s(i)=(i+1)&1 -> flash shifted reads are 8B aligned
__device__ float g_pos[(size_t)64 * 1024 * PITCH];

// ------------------------------ helpers -----------------------------------
__device__ __forceinline__ uint32_t smem_u32(const void* p) {
    uint32_t a;
    asm("{ .reg .u64 t; cvta.to.shared.u64 t, %1; cvt.u32.u64 %0, t; }" : "=r"(a) : "l"(p));
    return a;
}
__device__ __forceinline__ void ldsm4(uint32_t* r, uint32_t a) {
    asm volatile("ldmatrix.sync.aligned.m8n8.x4.shared.b16 {%0,%1,%2,%3}, [%4];"
        : "=r"(r[0]), "=r"(r[1]), "=r"(r[2]), "=r"(r[3]) : "r"(a));
}
__device__ __forceinline__ void ldsm2(uint32_t* r, uint32_t a) {
    asm volatile("ldmatrix.sync.aligned.m8n8.x2.shared.b16 {%0,%1}, [%2];"
        : "=r"(r[0]), "=r"(r[1]) : "r"(a));
}
__device__ __forceinline__ void mma16816(float* c, const uint32_t* a, const uint32_t* b) {
    asm volatile("mma.sync.aligned.m16n8k16.row.col.f32.bf16.bf16.f32 "
        "{%0,%1,%2,%3}, {%4,%5,%6,%7}, {%8,%9}, {%0,%1,%2,%3};"
        : "+f"(c[0]), "+f"(c[1]), "+f"(c[2]), "+f"(c[3])
        : "r"(a[0]), "r"(a[1]), "r"(a[2]), "r"(a[3]), "r"(b[0]), "r"(b[1]));
}
__device__ __forceinline__ void splitpair(float a, float b, uint32_t& hi, uint32_t& lo) {
    __nv_bfloat16 ah = __float2bfloat16_rn(a), bh = __float2bfloat16_rn(b);
    __nv_bfloat16 al = __float2bfloat16_rn(a - __bfloat162float(ah));
    __nv_bfloat16 bl = __float2bfloat16_rn(b - __bfloat162float(bh));
    __nv_bfloat162 h2, l2; h2.x = ah; h2.y = bh; l2.x = al; l2.y = bl;
    hi = *reinterpret_cast<uint32_t*>(&h2); lo = *reinterpret_cast<uint32_t*>(&l2);
}
__device__ __forceinline__ float posval(const float* pb, int i, int j) {
    if (j <= i)     return pb[(size_t)i * PITCH + (1023 + j - i + ((i + 1) & 1))];
    if (j == i + 1) return 0.0f;
    return pb[(size_t)(i + 1) * PITCH + (j - i - 2 + ((i + 2) & 1))];
}
__device__ __forceinline__ float2 pos2(const float* pb, int i, int j) {
    if (j + 1 <= i)
        return *(const float2*)(pb + (size_t)i * PITCH + (1023 - i + ((i + 1) & 1)) + j);
    if (j >= i + 2)
        return *(const float2*)(pb + (size_t)(i + 1) * PITCH + (((i + 2) & 1) - i - 2) + j);
    float2 r;
    r.x = posval(pb, i, j);
    r.y = posval(pb, i, j + 1);
    return r;
}

// ---------------------------------------------------------------------------
// Kernel 1: g_pos(shifted) = (q*0.125 + vbias) . R^T  via mma.sync bf16x3.
// Tile 128(i) x 64(t). grid (16 t, 8 i, 64 n), 256 thr = 8 warps 2(M)x4(N).
// ---------------------------------------------------------------------------
#define PQH 0
#define PQL 18432
#define PRH 36864
#define PRL 46080
#define POS_SMEM 55296

__global__ __launch_bounds__(256)
void pos_mma(const float* __restrict__ q, const float* __restrict__ vbias,
             const float* __restrict__ R)
{
    extern __shared__ char cb[];
    uint32_t sb = smem_u32(cb);

    const int tid = threadIdx.x, lane = tid & 31, wid = tid >> 5;
    const int wm = wid >> 2, wn = wid & 3;
    const int n = blockIdx.z, h = n & 15;
    const int i0 = blockIdx.y << 7, t0 = blockIdx.x << 6;

    const float* qb = q + (size_t)n * 65536 + (size_t)i0 * 64;
    const float* rb = R + (size_t)h * (2048 * 64) + (size_t)t0 * 64;

    #pragma unroll
    for (int it = 0; it < 8; ++it) {
        int fi = it * 256 + tid;
        int r = fi >> 4, d = (fi & 15) << 2;
        float4 f = *(const float4*)(qb + r * 64 + d);
        float4 bs = *(const float4*)(vbias + h * 64 + d);
        f.x = f.x * 0.125f + bs.x; f.y = f.y * 0.125f + bs.y;
        f.z = f.z * 0.125f + bs.z; f.w = f.w * 0.125f + bs.w;
        uint2 H, L;
        splitpair(f.x, f.y, H.x, L.x); splitpair(f.z, f.w, H.y, L.y);
        *(uint2*)(cb + PQH + r * 144 + d * 2) = H;
        *(uint2*)(cb + PQL + r * 144 + d * 2) = L;
    }
    #pragma unroll
    for (int it = 0; it < 4; ++it) {
        int fi = it * 256 + tid;
        int r = fi >> 4, d = (fi & 15) << 2;
        float4 g = *(const float4*)(rb + r * 64 + d);
        uint2 H, L;
        splitpair(g.x, g.y, H.x, L.x); splitpair(g.z, g.w, H.y, L.y);
        *(uint2*)(cb + PRH + r * 144 + d * 2) = H;
        *(uint2*)(cb + PRL + r * 144 + d * 2) = L;
    }
    __syncthreads();

    float C[4][2][4] = {};

    #pragma unroll
    for (int ks = 0; ks < 4; ++ks) {
        uint32_t a[4][4], bh[2][2], bl[2][2];
        #pragma unroll
        for (int mt = 0; mt < 4; ++mt)
            ldsm4(a[mt], sb + PQH + (wm * 64 + mt * 16 + (lane & 15)) * 144 +
                         (ks * 16 + ((lane >> 4) << 3)) * 2);
        #pragma unroll
        for (int nt = 0; nt < 2; ++nt) {
            uint32_t ao = (wn * 16 + nt * 8 + (lane & 7)) * 144 +
                          (ks * 16 + (((lane >> 3) & 1) << 3)) * 2;
            ldsm2(bh[nt], sb + PRH + ao);
            ldsm2(bl[nt], sb + PRL + ao);
        }
        #pragma unroll
        for (int mt = 0; mt < 4; ++mt)
            #pragma unroll
            for (int nt = 0; nt < 2; ++nt) {
                mma16816(C[mt][nt], a[mt], bh[nt]);
                mma16816(C[mt][nt], a[mt], bl[nt]);
            }
    }
    #pragma unroll
    for (int ks = 0; ks < 4; ++ks) {
        uint32_t a[4][4], bh[2][2];
        #pragma unroll
        for (int mt = 0; mt < 4; ++mt)
            ldsm4(a[mt], sb + PQL + (wm * 64 + mt * 16 + (lane & 15)) * 144 +
                         (ks * 16 + ((lane >> 4) << 3)) * 2);
        #pragma unroll
        for (int nt = 0; nt < 2; ++nt)
            ldsm2(bh[nt], sb + PRH + (wn * 16 + nt * 8 + (lane & 7)) * 144 +
                          (ks * 16 + (((lane >> 3) & 1) << 3)) * 2);
        #pragma unroll
        for (int mt = 0; mt < 4; ++mt)
            #pragma unroll
            for (int nt = 0; nt < 2; ++nt)
                mma16816(C[mt][nt], a[mt], bh[nt]);
    }

    float* gpn = g_pos + (size_t)n * (1024 * PITCH);
    #pragma unroll
    for (int mt = 0; mt < 4; ++mt) {
        const int i1 = i0 + wm * 64 + mt * 16 + (lane >> 2);
        const int i2 = i1 + 8;
        float* r1 = gpn + (size_t)i1 * PITCH + ((i1 + 1) & 1);
        float* r2 = gpn + (size_t)i2 * PITCH + ((i2 + 1) & 1);
        #pragma unroll
        for (int nt = 0; nt < 2; ++nt) {
            const int jc = t0 + wn * 16 + nt * 8 + ((lane & 3) << 1);
            r1[jc] = C[mt][nt][0]; r1[jc + 1] = C[mt][nt][1];
            r2[jc] = C[mt][nt][2]; r2[jc + 1] = C[mt][nt][3];
        }
    }
}

// ---------------------------------------------------------------------------
// Kernel 2: flash attention, bf16x3, P kept in registers (FA2 style).
// BM=128(i), BN=64(j), 16 iters. 512 thr = 16 warps as 8(M)x2(N).
// S: warp tile 16(i)x32(j). PV: warp k-slice 32(j), output 16(i)x64(d).
// Final O = sum of the 2 wn-partials via smem. grid (8 i-tiles, 64 n).
// ---------------------------------------------------------------------------
#define QUH_O 0
#define QUL_O 18432
#define KH_O  36864
#define KL_O  46080
#define VTH_O 55296
#define VTL_O 64512
#define LS_O  73728
#define OB_O  36864              /* 32KB overlay on K/V region, used post-loop */
#define FLASH_SMEM (LS_O + 2048)

__global__ __launch_bounds__(512)
void flash_mma(const float* __restrict__ q, const float* __restrict__ k,
               const float* __restrict__ v, const float* __restrict__ ubias,
               float* __restrict__ out)
{
    extern __shared__ char cb[];
    uint32_t sb = smem_u32(cb);

    const int tid = threadIdx.x, lane = tid & 31, wid = tid >> 5;
    const int wm = wid >> 1, wn = wid & 1;       // 8 M-rows x 2 N-cols
    const int n = blockIdx.y, h = n & 15;
    const int i0 = blockIdx.x << 7;

    // stage Qu = q*0.125 + u_bias (hi/lo)
    const float* qb = q + (size_t)n * 65536 + (size_t)i0 * 64;
    #pragma unroll
    for (int it = 0; it < 4; ++it) {
        int fi = it * 512 + tid;
        int r = fi >> 4, d = (fi & 15) << 2;
        float4 f = *(const float4*)(qb + r * 64 + d);
        float4 bs = *(const float4*)(ubias + h * 64 + d);
        f.x = f.x * 0.125f + bs.x; f.y = f.y * 0.125f + bs.y;
        f.z = f.z * 0.125f + bs.z; f.w = f.w * 0.125f + bs.w;
        uint2 H, L;
        splitpair(f.x, f.y, H.x, L.x); splitpair(f.z, f.w, H.y, L.y);
        *(uint2*)(cb + QUH_O + r * 144 + d * 2) = H;
        *(uint2*)(cb + QUL_O + r * 144 + d * 2) = L;
    }

    float oC[8][4] = {};        // 16(i) x 64(d) partial over this warp's j-slices
    float ls[2] = {};           // row sums (rows g, g+8)
    const float* pb  = g_pos + (size_t)n * (1024 * PITCH);
    const float* kb0 = k + (size_t)n * 65536;
    const float* vb0 = v + (size_t)n * 65536;

    const int g = lane >> 2, t4 = lane & 3;
    const int i1 = i0 + wm * 16 + g;            // this thread's row 1
    const int i2 = i1 + 8;                      // row 2

    for (int kt = 0; kt < 16; ++kt) {
        __syncthreads();   // prev PV done reading K/V before restage

        // ---- prefetch shifted pos values (latency overlaps staging) ----
        float pr[4][4];
        #pragma unroll
        for (int nt = 0; nt < 4; ++nt) {
            const int j = (kt << 6) + wn * 32 + nt * 8 + (t4 << 1);
            float2 pp = pos2(pb, i1, j);
            pr[nt][0] = pp.x; pr[nt][1] = pp.y;
            pp = pos2(pb, i2, j);
            pr[nt][2] = pp.x; pr[nt][3] = pp.y;
        }

        // ---- stage K (hi/lo, [j][72]bf16) and V^T (hi/lo, [d][72]bf16) ----
        const float* kb = kb0 + ((size_t)kt << 12);
        const float* vb = vb0 + ((size_t)kt << 12);
        #pragma unroll
        for (int it = 0; it < 2; ++it) {
            int fi = it * 512 + tid;
            int r = fi >> 4, d = (fi & 15) << 2;
            float4 f = *(const float4*)(kb + r * 64 + d);
            uint2 H, L;
            splitpair(f.x, f.y, H.x, L.x); splitpair(f.z, f.w, H.y, L.y);
            *(uint2*)(cb + KH_O + r * 144 + d * 2) = H;
            *(uint2*)(cb + KL_O + r * 144 + d * 2) = L;
            float4 gg = *(const float4*)(vb + r * 64 + d);
            float gv[4] = {gg.x, gg.y, gg.z, gg.w};
            #pragma unroll
            for (int rr = 0; rr < 4; ++rr) {
                int dd = d + rr;
                __nv_bfloat16 hh = __float2bfloat16_rn(gv[rr]);
                __nv_bfloat16 ll = __float2bfloat16_rn(gv[rr] - __bfloat162float(hh));
                *(__nv_bfloat16*)(cb + VTH_O + dd * 144 + r * 2) = hh;
                *(__nv_bfloat16*)(cb + VTL_O + dd * 144 + r * 2) = ll;
            }
        }
        __syncthreads();

        // ---- S = Qu . K^T  (bf16x3, single ks loop holding hi+lo) ----
        float sC[4][4] = {};
        #pragma unroll
        for (int ks = 0; ks < 4; ++ks) {
            uint32_t qh[4], ql[4], kh[4][2], kl[4][2];
            uint32_t qa = (wm * 16 + (lane & 15)) * 144 +
                          (ks * 16 + ((lane >> 4) << 3)) * 2;
            ldsm4(qh, sb + QUH_O + qa);
            ldsm4(ql, sb + QUL_O + qa);
            #pragma unroll
            for (int nt = 0; nt < 4; ++nt) {
                uint32_t ao = (wn * 32 + nt * 8 + (lane & 7)) * 144 +
                              (ks * 16 + (((lane >> 3) & 1) << 3)) * 2;
                ldsm2(kh[nt], sb + KH_O + ao);
                ldsm2(kl[nt], sb + KL_O + ao);
            }
            #pragma unroll
            for (int nt = 0; nt < 4; ++nt) {
                mma16816(sC[nt], qh, kh[nt]);
                mma16816(sC[nt], qh, kl[nt]);
                mma16816(sC[nt], ql, kh[nt]);
            }
        }

        // ---- exp(S + pos) and pack directly into A fragments (no smem P) ----
        uint32_t aH[2][4], aL[2][4];
        #pragma unroll
        for (int nt = 0; nt < 4; ++nt) {
            float e0 = __expf(sC[nt][0] + pr[nt][0]);
            float e1 = __expf(sC[nt][1] + pr[nt][1]);
            float e2 = __expf(sC[nt][2] + pr[nt][2]);
            float e3 = __expf(sC[nt][3] + pr[nt][3]);
            ls[0] += e0 + e1;
            ls[1] += e2 + e3;
            const int kk = nt >> 1, half = (nt & 1) << 1;
            splitpair(e0, e1, aH[kk][half + 0], aL[kk][half + 0]);   // row g,  k lo/hi half
            splitpair(e2, e3, aH[kk][half + 1], aL[kk][half + 1]);   // row g+8
        }
        // A-frag order per chunk kk: a0=(g, k0..7 via nt even c0c1), a1=(g+8 same),
        // a2=(g, k8..15 via nt odd), a3=(g+8 same):
        // built above: aH[kk] = { nt=2kk:(e0e1), nt=2kk:(e2e3), nt=2kk+1:(e0e1), nt=2kk+1:(e2e3) }

        // ---- O += P . V  (P in regs; k-slice = wn*32..+32; full d=64) ----
        #pragma unroll
        for (int kk = 0; kk < 2; ++kk) {
            #pragma unroll
            for (int dn = 0; dn < 8; ++dn) {
                uint32_t vh[2], vl[2];
                uint32_t ao = (dn * 8 + (lane & 7)) * 144 +
                              (wn * 32 + kk * 16 + (((lane >> 3) & 1) << 3)) * 2;
                ldsm2(vh, sb + VTH_O + ao);
                ldsm2(vl, sb + VTL_O + ao);
                mma16816(oC[dn], aH[kk], vh);
                mma16816(oC[dn], aH[kk], vl);
                mma16816(oC[dn], aL[kk], vh);
            }
        }
    }

    // ---- row-sum reduction: quad lanes, then the 2 wn warps via smem ----
    float* lsm = (float*)(cb + LS_O);
    #pragma unroll
    for (int p = 0; p < 2; ++p) {
        float vv = ls[p];
        vv += __shfl_xor_sync(0xffffffffu, vv, 1);
        vv += __shfl_xor_sync(0xffffffffu, vv, 2);
        ls[p] = vv;
    }
    __syncthreads();   // all PV reads of K/V done before Obuf overlay + lsm
    if ((lane & 3) == 0) {
        lsm[wn * 128 + wm * 16 + g] = ls[0];
        lsm[wn * 128 + wm * 16 + 8 + g] = ls[1];
    }

    // ---- O partial reduction across the 2 wn warps ----
    float* ob = (float*)(cb + OB_O);
    if (wn == 1) {
        #pragma unroll
        for (int dn = 0; dn < 8; ++dn) {
            const int col = dn * 8 + (t4 << 1);
            *(float2*)&ob[(wm * 16 + g) * 64 + col] = make_float2(oC[dn][0], oC[dn][1]);
            *(float2*)&ob[(wm * 16 + 8 + g) * 64 + col] = make_float2(oC[dn][2], oC[dn][3]);
        }
    }
    __syncthreads();
    if (wn == 0) {
        const int r1 = wm * 16 + g, r2 = r1 + 8;
        const float inv1 = 1.0f / (lsm[r1] + lsm[128 + r1]);
        const float inv2 = 1.0f / (lsm[r2] + lsm[128 + r2]);
        float* ob1 = out + (size_t)n * 65536 + (size_t)(i0 + r1) * 64;
        float* ob2 = out + (size_t)n * 65536 + (size_t)(i0 + r2) * 64;
        #pragma unroll
        for (int dn = 0; dn < 8; ++dn) {
            const int col = dn * 8 + (t4 << 1);
            float2 p1 = *(float2*)&ob[r1 * 64 + col];
            float2 p2 = *(float2*)&ob[r2 * 64 + col];
            *(float2*)(ob1 + col) = make_float2((oC[dn][0] + p1.x) * inv1,
                                                (oC[dn][1] + p1.y) * inv1);
            *(float2*)(ob2 + col) = make_float2((oC[dn][2] + p2.x) * inv2,
                                                (oC[dn][3] + p2.y) * inv2);
        }
    }
}

// ---------------------------------------------------------------------------
extern "C" void kernel_launch(void* const* d_in, const int* in_sizes, int n_in,
                              void* d_out, int out_size)
{
    const float* q  = (const float*)d_in[0];
    const float* k  = (const float*)d_in[1];
    const float* v  = (const float*)d_in[2];
    const float* ub = (const float*)d_in[3];
    const float* vb = (const float*)d_in[4];
    const float* R  = (const float*)d_in[5];
    float* out = (float*)d_out;

    cudaFuncSetAttribute(pos_mma, cudaFuncAttributeMaxDynamicSharedMemorySize, POS_SMEM);
    cudaFuncSetAttribute(flash_mma, cudaFuncAttributeMaxDynamicSharedMemorySize, FLASH_SMEM);

    pos_mma<<<dim3(16, 8, 64), 256, POS_SMEM>>>(q, vb, R);
    flash_mma<<<dim3(8, 64), 512, FLASH_SMEM>>>(q, k, v, ub, out);
}

// round 9
// speedup vs baseline: 1.2693x; 1.1965x over previous
#include <cuda_runtime.h>
#include <cuda_bf16.h>
#include <cstdint>

#define PITCH 1026
// g_pos[n][i][t + s(i)], s(i)=(i+1)&1 -> flash shifted reads are 8B aligned
__device__ float g_pos[(size_t)64 * 1024 * PITCH];
// preconverted operands for flash
__device__ __nv_bfloat16 g_kh[(size_t)64 * 1024 * 64];
__device__ __nv_bfloat16 g_kl[(size_t)64 * 1024 * 64];
__device__ __nv_bfloat16 g_vth[(size_t)64 * 64 * 1024];   // V^T: [n][d][j]
__device__ __nv_bfloat16 g_vtl[(size_t)64 * 64 * 1024];

// ------------------------------ helpers -----------------------------------
__device__ __forceinline__ uint32_t smem_u32(const void* p) {
    uint32_t a;
    asm("{ .reg .u64 t; cvta.to.shared.u64 t, %1; cvt.u32.u64 %0, t; }" : "=r"(a) : "l"(p));
    return a;
}
__device__ __forceinline__ void ldsm4(uint32_t* r, uint32_t a) {
    asm volatile("ldmatrix.sync.aligned.m8n8.x4.shared.b16 {%0,%1,%2,%3}, [%4];"
        : "=r"(r[0]), "=r"(r[1]), "=r"(r[2]), "=r"(r[3]) : "r"(a));
}
__device__ __forceinline__ void ldsm2(uint32_t* r, uint32_t a) {
    asm volatile("ldmatrix.sync.aligned.m8n8.x2.shared.b16 {%0,%1}, [%2];"
        : "=r"(r[0]), "=r"(r[1]) : "r"(a));
}
__device__ __forceinline__ void mma16816(float* c, const uint32_t* a, const uint32_t* b) {
    asm volatile("mma.sync.aligned.m16n8k16.row.col.f32.bf16.bf16.f32 "
        "{%0,%1,%2,%3}, {%4,%5,%6,%7}, {%8,%9}, {%0,%1,%2,%3};"
        : "+f"(c[0]), "+f"(c[1]), "+f"(c[2]), "+f"(c[3])
        : "r"(a[0]), "r"(a[1]), "r"(a[2]), "r"(a[3]), "r"(b[0]), "r"(b[1]));
}
__device__ __forceinline__ void splitpair(float a, float b, uint32_t& hi, uint32_t& lo) {
    __nv_bfloat16 ah = __float2bfloat16_rn(a), bh = __float2bfloat16_rn(b);
    __nv_bfloat16 al = __float2bfloat16_rn(a - __bfloat162float(ah));
    __nv_bfloat16 bl = __float2bfloat16_rn(b - __bfloat162float(bh));
    __nv_bfloat162 h2, l2; h2.x = ah; h2.y = bh; l2.x = al; l2.y = bl;
    hi = *reinterpret_cast<uint32_t*>(&h2); lo = *reinterpret_cast<uint32_t*>(&l2);
}
__device__ __forceinline__ float posval(const float* pb, int i, int j) {
    if (j <= i)     return pb[(size_t)i * PITCH + (1023 + j - i + ((i + 1) & 1))];
    if (j == i + 1) return 0.0f;
    return pb[(size_t)(i + 1) * PITCH + (j - i - 2 + ((i + 2) & 1))];
}
__device__ __forceinline__ float2 pos2(const float* pb, int i, int j) {
    if (j + 1 <= i)
        return *(const float2*)(pb + (size_t)i * PITCH + (1023 - i + ((i + 1) & 1)) + j);
    if (j >= i + 2)
        return *(const float2*)(pb + (size_t)(i + 1) * PITCH + (((i + 2) & 1) - i - 2) + j);
    float2 r;
    r.x = posval(pb, i, j);
    r.y = posval(pb, i, j + 1);
    return r;
}
#define CPA16(dst, src) asm volatile("cp.async.cg.shared.global [%0], [%1], 16;" :: "r"(dst), "l"(src))
#define CPA_COMMIT()    asm volatile("cp.async.commit_group;" ::: "memory")

// ---------------------------------------------------------------------------
// Kernel 0: preconvert K -> (hi,lo) bf16 [n][j][d]; V -> transposed (hi,lo)
// bf16 [n][d][j]. grid (16 jt, 64 n), 256 thr.
// ---------------------------------------------------------------------------
__global__ __launch_bounds__(256)
void prep_kv(const float* __restrict__ k, const float* __restrict__ v)
{
    __shared__ float vs[64 * 65];
    const int tid = threadIdx.x, n = blockIdx.y, jt = blockIdx.x;
    const float* kb = k + (size_t)n * 65536 + jt * 4096;
    const float* vb = v + (size_t)n * 65536 + jt * 4096;

    #pragma unroll
    for (int it = 0; it < 4; ++it) {
        int fi = it * 256 + tid;
        int r = fi >> 4, d = (fi & 15) << 2;
        float4 f = *(const float4*)(kb + r * 64 + d);
        uint32_t h0, l0, h1, l1;
        splitpair(f.x, f.y, h0, l0); splitpair(f.z, f.w, h1, l1);
        size_t o = (((size_t)n * 1024 + jt * 64 + r) << 6) + d;
        *(uint2*)(g_kh + o) = make_uint2(h0, h1);
        *(uint2*)(g_kl + o) = make_uint2(l0, l1);
        float4 g = *(const float4*)(vb + r * 64 + d);
        vs[r * 65 + d + 0] = g.x; vs[r * 65 + d + 1] = g.y;
        vs[r * 65 + d + 2] = g.z; vs[r * 65 + d + 3] = g.w;
    }
    __syncthreads();
    #pragma unroll
    for (int it = 0; it < 4; ++it) {
        int fi = it * 256 + tid;
        int d = fi >> 4, j = (fi & 15) << 2;
        float a0 = vs[(j + 0) * 65 + d], a1 = vs[(j + 1) * 65 + d];
        float a2 = vs[(j + 2) * 65 + d], a3 = vs[(j + 3) * 65 + d];
        uint32_t h0, l0, h1, l1;
        splitpair(a0, a1, h0, l0); splitpair(a2, a3, h1, l1);
        size_t o = (((size_t)n * 64 + d) << 10) + jt * 64 + j;
        *(uint2*)(g_vth + o) = make_uint2(h0, h1);
        *(uint2*)(g_vtl + o) = make_uint2(l0, l1);
    }
}

// ---------------------------------------------------------------------------
// Kernel 1: g_pos(shifted) = (q*0.125 + vbias) . R^T  via mma.sync bf16x3.
// Tile 128(i) x 64(t). grid (16 t, 8 i, 64 n), 256 thr = 8 warps 2(M)x4(N).
// Epilogue stages C in smem then writes coalesced rows.
// ---------------------------------------------------------------------------
#define PQH 0
#define PQL 18432
#define PRH 36864
#define PRL 46080
#define POS_SMEM 55296

__global__ __launch_bounds__(256)
void pos_mma(const float* __restrict__ q, const float* __restrict__ vbias,
             const float* __restrict__ R)
{
    extern __shared__ char cb[];
    uint32_t sb = smem_u32(cb);

    const int tid = threadIdx.x, lane = tid & 31, wid = tid >> 5;
    const int wm = wid >> 2, wn = wid & 3;
    const int n = blockIdx.z, h = n & 15;
    const int i0 = blockIdx.y << 7, t0 = blockIdx.x << 6;

    const float* qb = q + (size_t)n * 65536 + (size_t)i0 * 64;
    const float* rb = R + (size_t)h * (2048 * 64) + (size_t)t0 * 64;

    #pragma unroll
    for (int it = 0; it < 8; ++it) {
        int fi = it * 256 + tid;
        int r = fi >> 4, d = (fi & 15) << 2;
        float4 f = *(const float4*)(qb + r * 64 + d);
        float4 bs = *(const float4*)(vbias + h * 64 + d);
        f.x = f.x * 0.125f + bs.x; f.y = f.y * 0.125f + bs.y;
        f.z = f.z * 0.125f + bs.z; f.w = f.w * 0.125f + bs.w;
        uint2 H, L;
        splitpair(f.x, f.y, H.x, L.x); splitpair(f.z, f.w, H.y, L.y);
        *(uint2*)(cb + PQH + r * 144 + d * 2) = H;
        *(uint2*)(cb + PQL + r * 144 + d * 2) = L;
    }
    #pragma unroll
    for (int it = 0; it < 4; ++it) {
        int fi = it * 256 + tid;
        int r = fi >> 4, d = (fi & 15) << 2;
        float4 g = *(const float4*)(rb + r * 64 + d);
        uint2 H, L;
        splitpair(g.x, g.y, H.x, L.x); splitpair(g.z, g.w, H.y, L.y);
        *(uint2*)(cb + PRH + r * 144 + d * 2) = H;
        *(uint2*)(cb + PRL + r * 144 + d * 2) = L;
    }
    __syncthreads();

    float C[4][2][4] = {};

    #pragma unroll
    for (int ks = 0; ks < 4; ++ks) {
        uint32_t a[4][4], bh[2][2], bl[2][2];
        #pragma unroll
        for (int mt = 0; mt < 4; ++mt)
            ldsm4(a[mt], sb + PQH + (wm * 64 + mt * 16 + (lane & 15)) * 144 +
                         (ks * 16 + ((lane >> 4) << 3)) * 2);
        #pragma unroll
        for (int nt = 0; nt < 2; ++nt) {
            uint32_t ao = (wn * 16 + nt * 8 + (lane & 7)) * 144 +
                          (ks * 16 + (((lane >> 3) & 1) << 3)) * 2;
            ldsm2(bh[nt], sb + PRH + ao);
            ldsm2(bl[nt], sb + PRL + ao);
        }
        #pragma unroll
        for (int mt = 0; mt < 4; ++mt)
            #pragma unroll
            for (int nt = 0; nt < 2; ++nt) {
                mma16816(C[mt][nt], a[mt], bh[nt]);
                mma16816(C[mt][nt], a[mt], bl[nt]);
            }
    }
    #pragma unroll
    for (int ks = 0; ks < 4; ++ks) {
        uint32_t a[4][4], bh[2][2];
        #pragma unroll
        for (int mt = 0; mt < 4; ++mt)
            ldsm4(a[mt], sb + PQL + (wm * 64 + mt * 16 + (lane & 15)) * 144 +
                         (ks * 16 + ((lane >> 4) << 3)) * 2);
        #pragma unroll
        for (int nt = 0; nt < 2; ++nt)
            ldsm2(bh[nt], sb + PRH + (wn * 16 + nt * 8 + (lane & 7)) * 144 +
                          (ks * 16 + (((lane >> 3) & 1) << 3)) * 2);
        #pragma unroll
        for (int mt = 0; mt < 4; ++mt)
            #pragma unroll
            for (int nt = 0; nt < 2; ++nt)
                mma16816(C[mt][nt], a[mt], bh[nt]);
    }

    // ---- stage C in smem (overlays PQH/PQL), then coalesced copy-out ----
    __syncthreads();
    float* Ps = (float*)cb;   // 128 x 68 floats = 34816 B < 36864
    #pragma unroll
    for (int mt = 0; mt < 4; ++mt) {
        const int r1 = wm * 64 + mt * 16 + (lane >> 2);
        const int c = wn * 16 + ((lane & 3) << 1);
        #pragma unroll
        for (int nt = 0; nt < 2; ++nt) {
            Ps[r1 * 68 + c + nt * 8]           = C[mt][nt][0];
            Ps[r1 * 68 + c + nt * 8 + 1]       = C[mt][nt][1];
            Ps[(r1 + 8) * 68 + c + nt * 8]     = C[mt][nt][2];
            Ps[(r1 + 8) * 68 + c + nt * 8 + 1] = C[mt][nt][3];
        }
    }
    __syncthreads();
    float* gpn = g_pos + (size_t)n * (1024 * PITCH);
    #pragma unroll
    for (int rr = 0; rr < 16; ++rr) {
        const int r = (wid << 4) + rr;
        const int i = i0 + r;
        float* gp = gpn + (size_t)i * PITCH + t0 + ((i + 1) & 1);
        gp[lane]      = Ps[r * 68 + lane];
        gp[lane + 32] = Ps[r * 68 + lane + 32];
    }
}

// ---------------------------------------------------------------------------
// Kernel 2: flash attention, bf16x3, P in registers, double-buffered cp.async
// staging of preconverted K/V^T tiles. BM=128(i), BN=64(j), 16 iters.
// 512 thr = 16 warps as 8(M)x2(N). grid (8 i-tiles, 64 n).
// ---------------------------------------------------------------------------
#define QUH_O 0
#define QUL_O 18432
#define ST0_O 36864          /* stage: KH 0 | KL 9216 | VTH 18432 | VTL 27648 */
#define ST_SZ 36864
#define LS_O  110592
#define OB_O  36864          /* 32KB overlay on stage0 region, post-loop */
#define FLASH_SMEM (LS_O + 1024)

__global__ __launch_bounds__(512)
void flash_mma(const float* __restrict__ q, const float* __restrict__ ubias,
               float* __restrict__ out)
{
    extern __shared__ char cb[];
    uint32_t sb = smem_u32(cb);

    const int tid = threadIdx.x, lane = tid & 31, wid = tid >> 5;
    const int wm = wid >> 1, wn = wid & 1;       // 8 M-rows x 2 N-cols
    const int n = blockIdx.y, h = n & 15;
    const int i0 = blockIdx.x << 7;

    // stage Qu = q*0.125 + u_bias (hi/lo)
    const float* qb = q + (size_t)n * 65536 + (size_t)i0 * 64;
    #pragma unroll
    for (int it = 0; it < 4; ++it) {
        int fi = it * 512 + tid;
        int r = fi >> 4, d = (fi & 15) << 2;
        float4 f = *(const float4*)(qb + r * 64 + d);
        float4 bs = *(const float4*)(ubias + h * 64 + d);
        f.x = f.x * 0.125f + bs.x; f.y = f.y * 0.125f + bs.y;
        f.z = f.z * 0.125f + bs.z; f.w = f.w * 0.125f + bs.w;
        uint2 H, L;
        splitpair(f.x, f.y, H.x, L.x); splitpair(f.z, f.w, H.y, L.y);
        *(uint2*)(cb + QUH_O + r * 144 + d * 2) = H;
        *(uint2*)(cb + QUL_O + r * 144 + d * 2) = L;
    }

    float oC[8][4] = {};        // 16(i) x 64(d) partial over this warp's j-slices
    float ls[2] = {};           // row sums (rows g, g+8)
    const float* pb = g_pos + (size_t)n * (1024 * PITCH);

    const int g = lane >> 2, t4 = lane & 3;
    const int i1 = i0 + wm * 16 + g;
    const int i2 = i1 + 8;

    // cp.async chunk assignment: thread -> (row, 16B offset); 1 chunk/tile
    const int cr = tid >> 3;
    const int coff = (tid & 7) << 4;
    const char* khb = (const char*)(g_kh + (((size_t)n * 1024 + cr) << 6)) + coff;
    const char* klb = (const char*)(g_kl + (((size_t)n * 1024 + cr) << 6)) + coff;
    const char* vhb = (const char*)(g_vth + (((size_t)n * 64 + cr) << 10)) + coff;
    const char* vlb = (const char*)(g_vtl + (((size_t)n * 64 + cr) << 10)) + coff;
    const uint32_t sdst = sb + cr * 144 + coff;

    // issue stage for tile kt into buffer st (byte offset)
    #define ISSUE(kt, st) do {                                              \
        CPA16(sdst + (st) + 0,     khb + ((size_t)(kt) << 13));             \
        CPA16(sdst + (st) + 9216,  klb + ((size_t)(kt) << 13));             \
        CPA16(sdst + (st) + 18432, vhb + ((size_t)(kt) << 7));              \
        CPA16(sdst + (st) + 27648, vlb + ((size_t)(kt) << 7));              \
        CPA_COMMIT();                                                       \
    } while (0)

    ISSUE(0, ST0_O);

    for (int kt = 0; kt < 16; ++kt) {
        const uint32_t st = ST0_O + (kt & 1) * ST_SZ;

        // ---- prefetch shifted pos values (overlaps cp.async + compute) ----
        float pr[4][4];
        #pragma unroll
        for (int nt = 0; nt < 4; ++nt) {
            const int j = (kt << 6) + wn * 32 + nt * 8 + (t4 << 1);
            float2 pp = pos2(pb, i1, j);
            pr[nt][0] = pp.x; pr[nt][1] = pp.y;
            pp = pos2(pb, i2, j);
            pr[nt][2] = pp.x; pr[nt][3] = pp.y;
        }

        if (kt < 15) {
            ISSUE(kt + 1, ST0_O + ((kt + 1) & 1) * ST_SZ);
            asm volatile("cp.async.wait_group 1;" ::: "memory");
        } else {
            asm volatile("cp.async.wait_group 0;" ::: "memory");
        }
        __syncthreads();

        // ---- S = Qu . K^T  (bf16x3) ----
        float sC[4][4] = {};
        #pragma unroll
        for (int ks = 0; ks < 4; ++ks) {
            uint32_t qh[4], ql[4], kh[4][2], kl[4][2];
            uint32_t qa = (wm * 16 + (lane & 15)) * 144 +
                          (ks * 16 + ((lane >> 4) << 3)) * 2;
            ldsm4(qh, sb + QUH_O + qa);
            ldsm4(ql, sb + QUL_O + qa);
            #pragma unroll
            for (int nt = 0; nt < 4; ++nt) {
                uint32_t ao = (wn * 32 + nt * 8 + (lane & 7)) * 144 +
                              (ks * 16 + (((lane >> 3) & 1) << 3)) * 2;
                ldsm2(kh[nt], st + ao + sb);
                ldsm2(kl[nt], st + ao + sb + 9216);
            }
            #pragma unroll
            for (int nt = 0; nt < 4; ++nt) {
                mma16816(sC[nt], qh, kh[nt]);
                mma16816(sC[nt], qh, kl[nt]);
                mma16816(sC[nt], ql, kh[nt]);
            }
        }

        // ---- exp(S + pos), pack into A fragments (no smem P) ----
        uint32_t aH[2][4], aL[2][4];
        #pragma unroll
        for (int nt = 0; nt < 4; ++nt) {
            float e0 = __expf(sC[nt][0] + pr[nt][0]);
            float e1 = __expf(sC[nt][1] + pr[nt][1]);
            float e2 = __expf(sC[nt][2] + pr[nt][2]);
            float e3 = __expf(sC[nt][3] + pr[nt][3]);
            ls[0] += e0 + e1;
            ls[1] += e2 + e3;
            const int kk = nt >> 1, half = (nt & 1) << 1;
            splitpair(e0, e1, aH[kk][half + 0], aL[kk][half + 0]);
            splitpair(e2, e3, aH[kk][half + 1], aL[kk][half + 1]);
        }

        // ---- O += P . V  (P in regs; k-slice = wn*32..+32; full d=64) ----
        #pragma unroll
        for (int kk = 0; kk < 2; ++kk) {
            #pragma unroll
            for (int dn = 0; dn < 8; ++dn) {
                uint32_t vh[2], vl[2];
                uint32_t ao = (dn * 8 + (lane & 7)) * 144 +
                              (wn * 32 + kk * 16 + (((lane >> 3) & 1) << 3)) * 2;
                ldsm2(vh, st + ao + sb + 18432);
                ldsm2(vl, st + ao + sb + 27648);
                mma16816(oC[dn], aH[kk], vh);
                mma16816(oC[dn], aH[kk], vl);
                mma16816(oC[dn], aL[kk], vh);
            }
        }
        __syncthreads();   // all reads of buffer done before it is re-issued
    }

    // ---- row-sum reduction: quad lanes, then the 2 wn warps via smem ----
    float* lsm = (float*)(cb + LS_O);
    #pragma unroll
    for (int p = 0; p < 2; ++p) {
        float vv = ls[p];
        vv += __shfl_xor_sync(0xffffffffu, vv, 1);
        vv += __shfl_xor_sync(0xffffffffu, vv, 2);
        ls[p] = vv;
    }
    if ((lane & 3) == 0) {
        lsm[wn * 128 + wm * 16 + g] = ls[0];
        lsm[wn * 128 + wm * 16 + 8 + g] = ls[1];
    }

    // ---- O partial reduction across the 2 wn warps ----
    float* ob = (float*)(cb + OB_O);
    if (wn == 1) {
        #pragma unroll
        for (int dn = 0; dn < 8; ++dn) {
            const int col = dn * 8 + (t4 << 1);
            *(float2*)&ob[(wm * 16 + g) * 64 + col] = make_float2(oC[dn][0], oC[dn][1]);
            *(float2*)&ob[(wm * 16 + 8 + g) * 64 + col] = make_float2(oC[dn][2], oC[dn][3]);
        }
    }
    __syncthreads();
    if (wn == 0) {
        const int r1 = wm * 16 + g, r2 = r1 + 8;
        const float inv1 = 1.0f / (lsm[r1] + lsm[128 + r1]);
        const float inv2 = 1.0f / (lsm[r2] + lsm[128 + r2]);
        float* ob1 = out + (size_t)n * 65536 + (size_t)(i0 + r1) * 64;
        float* ob2 = out + (size_t)n * 65536 + (size_t)(i0 + r2) * 64;
        #pragma unroll
        for (int dn = 0; dn < 8; ++dn) {
            const int col = dn * 8 + (t4 << 1);
            float2 p1 = *(float2*)&ob[r1 * 64 + col];
            float2 p2 = *(float2*)&ob[r2 * 64 + col];
            *(float2*)(ob1 + col) = make_float2((oC[dn][0] + p1.x) * inv1,
                                                (oC[dn][1] + p1.y) * inv1);
            *(float2*)(ob2 + col) = make_float2((oC[dn][2] + p2.x) * inv2,
                                                (oC[dn][3] + p2.y) * inv2);
        }
    }
}

// ---------------------------------------------------------------------------
extern "C" void kernel_launch(void* const* d_in, const int* in_sizes, int n_in,
                              void* d_out, int out_size)
{
    const float* q  = (const float*)d_in[0];
    const float* k  = (const float*)d_in[1];
    const float* v  = (const float*)d_in[2];
    const float* ub = (const float*)d_in[3];
    const float* vb = (const float*)d_in[4];
    const float* R  = (const float*)d_in[5];
    float* out = (float*)d_out;

    cudaFuncSetAttribute(pos_mma, cudaFuncAttributeMaxDynamicSharedMemorySize, POS_SMEM);
    cudaFuncSetAttribute(flash_mma, cudaFuncAttributeMaxDynamicSharedMemorySize, FLASH_SMEM);

    prep_kv<<<dim3(16, 64), 256>>>(k, v);
    pos_mma<<<dim3(16, 8, 64), 256, POS_SMEM>>>(q, vb, R);
    flash_mma<<<dim3(8, 64), 512, FLASH_SMEM>>>(q, ub, out);
}